// round 5
// baseline (speedup 1.0000x reference)
#include <cuda_runtime.h>
#include <cuda.h>
#include <cuda_bf16.h>
#include <cstdint>
#include <cstddef>

// ---------------------------------------------------------------------------
// Problem constants
// ---------------------------------------------------------------------------
#define B_DIM 4096
#define F_DIM 4096
#define O_DIM 32000

static constexpr float SA_SCALE = 18.0f;                 // a int8 scale
static constexpr float OUT_SCALE = 1.0f / (18.0f * 128.0f);

// Scratch (device globals: allocation-free rule)
__device__ int8_t         g_a8[(size_t)B_DIM * F_DIM];   // int8 a ~= (x - mask)*18
__device__ int8_t         g_b8[(size_t)O_DIM * F_DIM];   // int8 b = sat((quant(w)-mask)*128)
__device__ __nv_bfloat16  g_bq[(size_t)O_DIM * F_DIM];   // bf16 b (EXACT multiples of 1/128)

// ---------------------------------------------------------------------------
// PTX helpers (baseline-PTX only: toolchain targets compute_103, no tcgen05)
// ---------------------------------------------------------------------------
__device__ __forceinline__ uint32_t smem_u32(const void* p) {
    uint32_t a;
    asm("{ .reg .u64 t; cvta.to.shared.u64 t, %1; cvt.u32.u64 %0, t; }"
        : "=r"(a) : "l"(p));
    return a;
}

__device__ __forceinline__ uint32_t elect1() {
    uint32_t r;
    asm volatile(
        "{\n\t.reg .pred p;\n\telect.sync _|p, 0xFFFFFFFF;\n\tselp.b32 %0, 1, 0, p;\n\t}"
        : "=r"(r));
    return r;
}

#define MBARRIER_INIT(addr, cnt) \
    asm volatile("mbarrier.init.shared.b64 [%0], %1;" :: "r"((uint32_t)(addr)), "r"((uint32_t)(cnt)) : "memory")

#define MBARRIER_ARRIVE(addr) \
    asm volatile("mbarrier.arrive.shared.b64 _, [%0];" :: "r"((uint32_t)(addr)) : "memory")

#define MBARRIER_EXPECT_TX(addr, bytes) \
    asm volatile("mbarrier.arrive.expect_tx.shared.b64 _, [%0], %1;" :: "r"((uint32_t)(addr)), "r"((uint32_t)(bytes)) : "memory")

#define MBARRIER_WAIT_PARITY(mbar, par) do { \
    uint32_t _m = (uint32_t)(mbar); uint32_t _p = (uint32_t)(par); uint32_t _d; \
    asm volatile("{\n\t.reg .pred p;\n\t" \
        "mbarrier.try_wait.parity.acquire.cta.shared::cta.b64 p, [%1], %2;\n\t" \
        "selp.b32 %0, 1, 0, p;\n\t}" : "=r"(_d) : "r"(_m), "r"(_p) : "memory"); \
    if (!_d) { \
        asm volatile("{\n\t.reg .pred P1;\n\t" \
            "WL_%=:\n\t" \
            "mbarrier.try_wait.parity.acquire.cta.shared::cta.b64 P1, [%0], %1, 0x989680;\n\t" \
            "@P1 bra.uni WD_%=;\n\t" \
            "bra.uni WL_%=;\n\t" \
            "WD_%=:\n\t}" :: "r"(_m), "r"(_p) : "memory"); \
    } \
} while (0)

#define MBARRIER_WAIT_PARITY_RELAXED(mbar, par) do { \
    uint32_t _m = (uint32_t)(mbar); uint32_t _p = (uint32_t)(par); uint32_t _d; \
    asm volatile("{\n\t.reg .pred p;\n\t" \
        "mbarrier.try_wait.parity.relaxed.cta.shared::cta.b64 p, [%1], %2, 0x989680;\n\t" \
        "selp.b32 %0, 1, 0, p;\n\t}" : "=r"(_d) : "r"(_m), "r"(_p) : "memory"); \
    if (!_d) { \
        asm volatile("{\n\t.reg .pred P1;\n\t" \
            "WL_%=:\n\t" \
            "mbarrier.try_wait.parity.relaxed.cta.shared::cta.b64 P1, [%0], %1, 0x989680;\n\t" \
            "@P1 bra.uni WD_%=;\n\t" \
            "bra.uni WL_%=;\n\t" \
            "WD_%=:\n\t}" :: "r"(_m), "r"(_p) : "memory"); \
    } \
} while (0)

__device__ __forceinline__ void tma2d(uint32_t dst, const CUtensorMap* m, int cx, int cy, uint32_t bar) {
    asm volatile(
        "cp.async.bulk.tensor.2d.shared::cta.global.tile.mbarrier::complete_tx::bytes "
        "[%0], [%1, {%2, %3}], [%4];"
        :: "r"(dst), "l"(m), "r"(cx), "r"(cy), "r"(bar) : "memory");
}

#define LDMATRIX_X4(r0, r1, r2, r3, addr) \
    asm volatile("ldmatrix.sync.aligned.m8n8.x4.shared.b16 {%0,%1,%2,%3}, [%4];" \
                 : "=r"(r0), "=r"(r1), "=r"(r2), "=r"(r3) : "r"(addr))

// int8 IMMA: m16n8k32, s32 accum (baseline PTX, sm_80+)
#define MMAI8(c, a, b) \
    asm volatile("mma.sync.aligned.m16n8k32.row.col.s32.s8.s8.s32 " \
                 "{%0,%1,%2,%3}, {%4,%5,%6,%7}, {%8,%9}, {%0,%1,%2,%3};" \
                 : "+r"((c)[0]), "+r"((c)[1]), "+r"((c)[2]), "+r"((c)[3]) \
                 : "r"((a)[0]), "r"((a)[1]), "r"((a)[2]), "r"((a)[3]), \
                   "r"((b)[0]), "r"((b)[1]))

__device__ __forceinline__ int sat127(int v) {
    return max(-127, min(127, v));
}
__device__ __forceinline__ uint32_t pack_s8_4(int v0, int v1, int v2, int v3) {
    return (uint32_t)(v0 & 0xFF) | ((uint32_t)(v1 & 0xFF) << 8) |
           ((uint32_t)(v2 & 0xFF) << 16) | ((uint32_t)(v3 & 0xFF) << 24);
}

// ---------------------------------------------------------------------------
// Prep kernels
// ---------------------------------------------------------------------------
__global__ void prep_a_kernel(const float4* __restrict__ x, const float4* __restrict__ mask) {
    size_t i = (size_t)blockIdx.x * blockDim.x + threadIdx.x;  // < B*F/4
    float4 xv = x[i], mv = mask[i];
    int v0 = sat127(__float2int_rn((xv.x - mv.x) * SA_SCALE));
    int v1 = sat127(__float2int_rn((xv.y - mv.y) * SA_SCALE));
    int v2 = sat127(__float2int_rn((xv.z - mv.z) * SA_SCALE));
    int v3 = sat127(__float2int_rn((xv.w - mv.w) * SA_SCALE));
    reinterpret_cast<uint32_t*>(g_a8)[i] = pack_s8_4(v0, v1, v2, v3);
}

__device__ __forceinline__ float quantw1(float w, float m) {
    float q = rintf(w * 128.0f) * 0.0078125f;     // round-half-even like jnp.round
    q = fminf(1.0f, fmaxf(-1.0f, q));
    return q - m;                                  // multiple of 1/128, exact in bf16
}

__global__ void prep_b_kernel(const float4* __restrict__ w, const float4* __restrict__ mask) {
    size_t i = (size_t)blockIdx.x * blockDim.x + threadIdx.x;  // < O*F/4
    float4 wv = w[i], mv = mask[i];
    float b0 = quantw1(wv.x, mv.x), b1 = quantw1(wv.y, mv.y);
    float b2 = quantw1(wv.z, mv.z), b3 = quantw1(wv.w, mv.w);
    // b*128 is exactly integer; saturate to int8 (error only on |b128|>127 tail)
    int i0 = sat127(__float2int_rn(b0 * 128.0f));
    int i1 = sat127(__float2int_rn(b1 * 128.0f));
    int i2 = sat127(__float2int_rn(b2 * 128.0f));
    int i3 = sat127(__float2int_rn(b3 * 128.0f));
    reinterpret_cast<uint32_t*>(g_b8)[i] = pack_s8_4(i0, i1, i2, i3);
    __nv_bfloat162* o = reinterpret_cast<__nv_bfloat162*>(&g_bq[4 * i]);
    __nv_bfloat162 p;
    p.x = __float2bfloat16(b0); p.y = __float2bfloat16(b1); o[0] = p;
    p.x = __float2bfloat16(b2); p.y = __float2bfloat16(b3); o[1] = p;
}

// ---------------------------------------------------------------------------
// GEMM: logits[B, O] ~= (a8 @ b8^T) / (18*128)  (int8 mma.sync, s32 accum)
// Tiles: BM=128, BN=256, BK=128 int8. 8 math warps (64x64 each) + 1 TMA warp.
// ---------------------------------------------------------------------------
static constexpr int BM = 128, BN = 256, BK = 128, STAGES = 4;
static constexpr int NCHUNK = F_DIM / BK;                          // 32
static constexpr uint32_t A_BYTES = BM * BK;                       // 16384
static constexpr uint32_t B_BYTES = BN * BK;                       // 32768
static constexpr uint32_t STAGE_BYTES = A_BYTES + B_BYTES;         // 49152
static constexpr uint32_t GEMM_SMEM = 1024 + STAGES * STAGE_BYTES; // 197632
static constexpr int GEMM_THREADS = 288;                           // 8 math + 1 producer warp

__global__ void __launch_bounds__(GEMM_THREADS, 1) sgxfl_gemm_kernel(
    const __grid_constant__ CUtensorMap tma_a,
    const __grid_constant__ CUtensorMap tma_b,
    float* __restrict__ out)
{
    extern __shared__ char smem[];
    const uint32_t sb = smem_u32(smem);
    const int tid = threadIdx.x;
    const int wid = tid >> 5, lid = tid & 31;

    // L2-friendly rasterization: GROUP_M=8 tiles of M per N sweep
    const int num_n = O_DIM / BN;   // 125
    const int GROUP = 8;
    const int cpg = GROUP * num_n;  // 1000
    const int g = blockIdx.x / cpg, r = blockIdx.x % cpg;
    const int m0 = (g * GROUP + (r % GROUP)) * BM;
    const int n0 = (r / GROUP) * BN;

    if (tid == 0) {
#pragma unroll
        for (int s = 0; s < STAGES; s++) {
            MBARRIER_INIT(sb + 16 * s, 1);       // full: tx-based
            MBARRIER_INIT(sb + 16 * s + 8, 8);   // empty: 8 math warps
        }
        asm volatile("fence.proxy.async.shared::cta;" ::: "memory");
    }
    __syncthreads();

    if (wid == 8) {
        // ---- TMA producer warp ----
        const uint32_t e1 = elect1();
        int st = 0, ph = 1;
        for (int i = 0; i < NCHUNK; i++) {
            MBARRIER_WAIT_PARITY_RELAXED(sb + 16 * st + 8, ph);
            if (e1) {
                MBARRIER_EXPECT_TX(sb + 16 * st, STAGE_BYTES);
                const uint32_t base = sb + 1024 + st * STAGE_BYTES;
                const int k0 = i * BK;
                tma2d(base,           &tma_a, k0, m0, sb + 16 * st);
                tma2d(base + A_BYTES, &tma_b, k0, n0, sb + 16 * st);
            }
            if (++st == STAGES) { st = 0; ph ^= 1; }
        }
        return;
    }

    // ---- Math warps (0..7): warp tile 64 (M) x 64 (N) ----
    const int wm = wid & 1;            // 0..1 -> M offset
    const int wn = wid >> 1;           // 0..3 -> N offset
    const int M0 = wm * 64;
    const int N0 = wn * 64;

    // ldmatrix per-lane offsets. Rows are 128 bytes (BK int8); SW128 swizzle:
    // byte offset XOR ((row & 7) << 4).  (layout verified in R4 with k32 fragments)
    const uint32_t xrA  = (uint32_t)(lid & 7) << 4;
    const uint32_t khxA = (uint32_t)(lid >> 4) * 16;
    uint32_t rowA[4];
#pragma unroll
    for (int mi = 0; mi < 4; mi++)
        rowA[mi] = (uint32_t)(M0 + mi * 16 + (lid & 15)) * 128;
    const uint32_t xrB = (uint32_t)(lid & 7) << 4;
    const uint32_t khB = (uint32_t)((lid >> 3) & 1) * 16;
    uint32_t rowB[4];
#pragma unroll
    for (int p = 0; p < 4; p++)
        rowB[p] = (uint32_t)(N0 + p * 16 + (lid & 7) + (lid >> 4) * 8) * 128;

    int acc[4][8][4];
#pragma unroll
    for (int mi = 0; mi < 4; mi++)
#pragma unroll
        for (int nj = 0; nj < 8; nj++)
#pragma unroll
            for (int q = 0; q < 4; q++) acc[mi][nj][q] = 0;

    int st = 0, ph = 0;
#pragma unroll 1
    for (int i = 0; i < NCHUNK; i++) {
        MBARRIER_WAIT_PARITY(sb + 16 * st, ph);
        const uint32_t base = sb + 1024 + st * STAGE_BYTES;
        const uint32_t sA = base, sB = base + A_BYTES;

#pragma unroll
        for (int k = 0; k < 4; k++) {     // 4 k-steps of 32 int8 (32 bytes) each
            const uint32_t colA = (uint32_t)(k * 32) + khxA;
            const uint32_t colB = (uint32_t)(k * 32) + khB;
            uint32_t af[4][4];
#pragma unroll
            for (int mi = 0; mi < 4; mi++) {
                LDMATRIX_X4(af[mi][0], af[mi][1], af[mi][2], af[mi][3],
                            sA + rowA[mi] + (colA ^ xrA));
            }
#pragma unroll
            for (int p = 0; p < 4; p++) {
                uint32_t b0[2], b1[2];
                LDMATRIX_X4(b0[0], b0[1], b1[0], b1[1],
                            sB + rowB[p] + (colB ^ xrB));
#pragma unroll
                for (int mi = 0; mi < 4; mi++) {
                    MMAI8(acc[mi][2 * p],     af[mi], b0);
                    MMAI8(acc[mi][2 * p + 1], af[mi], b1);
                }
            }
        }
        if (lid == 0) MBARRIER_ARRIVE(sb + 16 * st + 8);
        if (++st == STAGES) { st = 0; ph ^= 1; }
    }

    // ---- Epilogue: scale to fp32 logits, write gmem ----
    const int rg = lid >> 2;
    const int cg = (lid & 3) * 2;
#pragma unroll
    for (int mi = 0; mi < 4; mi++) {
        float* p0 = out + (size_t)(m0 + M0 + mi * 16 + rg) * O_DIM + (n0 + N0 + cg);
        float* p1 = p0 + (size_t)8 * O_DIM;
#pragma unroll
        for (int nj = 0; nj < 8; nj++) {
            *reinterpret_cast<float2*>(p0 + nj * 8) =
                make_float2(__int2float_rn(acc[mi][nj][0]) * OUT_SCALE,
                            __int2float_rn(acc[mi][nj][1]) * OUT_SCALE);
            *reinterpret_cast<float2*>(p1 + nj * 8) =
                make_float2(__int2float_rn(acc[mi][nj][2]) * OUT_SCALE,
                            __int2float_rn(acc[mi][nj][3]) * OUT_SCALE);
        }
    }
}

// ---------------------------------------------------------------------------
// Fused selective-correction + softmax.
// INT8 logits have error std ~2.1. Recompute all entries within DELTA of the
// row max exactly: a (fp32, from x-mask) dot b (bf16 g_bq, EXACT values).
// ---------------------------------------------------------------------------
__device__ __forceinline__ float fexp(float x) {  // x <= 0
    x = fmaxf(x, -87.0f);
    float t = x * 1.4426950408889634f;
    float fi = floorf(t);
    float f = t - fi;
    float p = 1.5403530e-4f;
    p = fmaf(p, f, 1.3333558e-3f);
    p = fmaf(p, f, 9.6181291e-3f);
    p = fmaf(p, f, 5.5504109e-2f);
    p = fmaf(p, f, 2.4022651e-1f);
    p = fmaf(p, f, 6.9314718e-1f);
    p = fmaf(p, f, 1.0f);
    int ei = (int)fi;
    float sc = __int_as_float((ei + 127) << 23);
    return p * sc;
}

static constexpr int   SMX_THREADS = 1024;
static constexpr int   SMX_NV4 = O_DIM / 4;        // 8000
static constexpr int   FIX_CAP = 2048;
static constexpr float FIX_DELTA = 40.0f;
// smem floats: row[32000] | a_row[4096] | red[64] | list[2048 ints] | cnt
static constexpr uint32_t SMX_ROW   = 0;
static constexpr uint32_t SMX_AROW  = O_DIM;                  // 32000
static constexpr uint32_t SMX_RED   = SMX_AROW + F_DIM;       // 36096
static constexpr uint32_t SMX_LIST  = SMX_RED + 64;           // 36160
static constexpr uint32_t SMX_CNT   = SMX_LIST + FIX_CAP;     // 38208
static constexpr uint32_t SMX_SMEM  = (SMX_CNT + 8) * 4;      // ~149.3 KB

__global__ void __launch_bounds__(SMX_THREADS, 1) softmax_fix_kernel(
    float* __restrict__ out,
    const float* __restrict__ x,
    const float* __restrict__ mask)
{
    extern __shared__ float sm[];
    float* srow  = sm + SMX_ROW;
    float* arow  = sm + SMX_AROW;
    float* red   = sm + SMX_RED;
    int*   list  = reinterpret_cast<int*>(sm + SMX_LIST);
    int*   cnt   = reinterpret_cast<int*>(sm + SMX_CNT);

    const int tid = threadIdx.x;
    const int wid = tid >> 5, lid = tid & 31;
    const int row = blockIdx.x;
    float* p = out + (size_t)row * O_DIM;
    float4* p4 = reinterpret_cast<float4*>(p);
    float4* s4 = reinterpret_cast<float4*>(srow);

    if (tid == 0) *cnt = 0;

    // stage a_row = x[row] - mask[row] (fp32, exact)
    {
        const float4* xr = reinterpret_cast<const float4*>(x + (size_t)row * F_DIM);
        const float4* mr = reinterpret_cast<const float4*>(mask + (size_t)row * F_DIM);
        for (int j = tid; j < F_DIM / 4; j += SMX_THREADS) {
            float4 xv = xr[j], mv = mr[j];
            reinterpret_cast<float4*>(arow)[j] =
                make_float4(xv.x - mv.x, xv.y - mv.y, xv.z - mv.z, xv.w - mv.w);
        }
    }

    // stage logits row, approximate max
    float m = -3.0e38f;
    for (int j = tid; j < SMX_NV4; j += SMX_THREADS) {
        float4 v = p4[j];
        s4[j] = v;
        m = fmaxf(m, fmaxf(fmaxf(v.x, v.y), fmaxf(v.z, v.w)));
    }
#pragma unroll
    for (int o = 16; o > 0; o >>= 1) m = fmaxf(m, __shfl_xor_sync(~0u, m, o));
    if (lid == 0) red[wid] = m;
    __syncthreads();
    float M0 = red[0];
#pragma unroll
    for (int k = 1; k < SMX_THREADS / 32; k++) M0 = fmaxf(M0, red[k]);

    // select candidates within DELTA of approx max
    const float thr = M0 - FIX_DELTA;
    for (int j = tid; j < O_DIM; j += SMX_THREADS) {
        if (srow[j] > thr) {
            int pos = atomicAdd(cnt, 1);
            if (pos < FIX_CAP) list[pos] = j;
        }
    }
    __syncthreads();
    int nsel = *cnt;
    if (nsel > FIX_CAP) nsel = FIX_CAP;

    // exact recompute of selected logits: one warp per dot, b from g_bq (bf16 exact)
    for (int s = wid; s < nsel; s += SMX_THREADS / 32) {
        const int col = list[s];
        const uint4* bq4 = reinterpret_cast<const uint4*>(g_bq + (size_t)col * F_DIM);
        float part = 0.0f;
#pragma unroll 4
        for (int it = 0; it < F_DIM / (8 * 32); it++) {   // 16 iters
            const int c = it * 32 + lid;                   // chunk of 8 bf16
            uint4 v = bq4[c];
            const float* ar = arow + 8 * c;
            part = fmaf(ar[0], __uint_as_float(v.x << 16), part);
            part = fmaf(ar[1], __uint_as_float(v.x & 0xffff0000u), part);
            part = fmaf(ar[2], __uint_as_float(v.y << 16), part);
            part = fmaf(ar[3], __uint_as_float(v.y & 0xffff0000u), part);
            part = fmaf(ar[4], __uint_as_float(v.z << 16), part);
            part = fmaf(ar[5], __uint_as_float(v.z & 0xffff0000u), part);
            part = fmaf(ar[6], __uint_as_float(v.w << 16), part);
            part = fmaf(ar[7], __uint_as_float(v.w & 0xffff0000u), part);
        }
#pragma unroll
        for (int o = 16; o > 0; o >>= 1) part += __shfl_xor_sync(~0u, part, o);
        if (lid == 0) srow[col] = part;
    }
    __syncthreads();

    // exact max over corrected row
    m = -3.0e38f;
    for (int j = tid; j < SMX_NV4; j += SMX_THREADS) {
        float4 v = s4[j];
        m = fmaxf(m, fmaxf(fmaxf(v.x, v.y), fmaxf(v.z, v.w)));
    }
#pragma unroll
    for (int o = 16; o > 0; o >>= 1) m = fmaxf(m, __shfl_xor_sync(~0u, m, o));
    if (lid == 0) red[wid] = m;
    __syncthreads();
    float M = red[0];
#pragma unroll
    for (int k = 1; k < SMX_THREADS / 32; k++) M = fmaxf(M, red[k]);

    // exp + sum
    float ssum = 0.0f;
    for (int j = tid; j < SMX_NV4; j += SMX_THREADS) {
        float4 v = s4[j];
        v.x = fexp(v.x - M); v.y = fexp(v.y - M);
        v.z = fexp(v.z - M); v.w = fexp(v.w - M);
        s4[j] = v;
        ssum += (v.x + v.y) + (v.z + v.w);
    }
#pragma unroll
    for (int o = 16; o > 0; o >>= 1) ssum += __shfl_xor_sync(~0u, ssum, o);
    if (lid == 0) red[32 + wid] = ssum;
    __syncthreads();
    float tot = 0.0f;
#pragma unroll
    for (int k = 0; k < SMX_THREADS / 32; k++) tot += red[32 + k];
    const float inv = 1.0f / tot;

    // normalize + write
    for (int j = tid; j < SMX_NV4; j += SMX_THREADS) {
        float4 v = s4[j];
        v.x *= inv; v.y *= inv; v.z *= inv; v.w *= inv;
        p4[j] = v;
    }
}

// ---------------------------------------------------------------------------
// Host launch
// ---------------------------------------------------------------------------
typedef CUresult (*EncodeTiledFn)(
    CUtensorMap*, CUtensorMapDataType, cuuint32_t, void*,
    const cuuint64_t*, const cuuint64_t*, const cuuint32_t*, const cuuint32_t*,
    CUtensorMapInterleave, CUtensorMapSwizzle, CUtensorMapL2promotion, CUtensorMapFloatOOBfill);

static void make_desc2d_u8(EncodeTiledFn enc, CUtensorMap* tm, void* base,
                           uint64_t d0, uint64_t d1, uint32_t b0, uint32_t b1) {
    cuuint64_t dims[2] = {d0, d1};
    cuuint64_t strides[1] = {d0};    // int8 = 1 byte/elem
    cuuint32_t box[2] = {b0, b1};
    cuuint32_t es[2] = {1, 1};
    enc(tm, CU_TENSOR_MAP_DATA_TYPE_UINT8, 2, base, dims, strides, box, es,
        CU_TENSOR_MAP_INTERLEAVE_NONE, CU_TENSOR_MAP_SWIZZLE_128B,
        CU_TENSOR_MAP_L2_PROMOTION_L2_128B, CU_TENSOR_MAP_FLOAT_OOB_FILL_NONE);
}

extern "C" void kernel_launch(void* const* d_in, const int* in_sizes, int n_in,
                              void* d_out, int out_size) {
    const float* x    = (const float*)d_in[0];
    const float* w    = (const float*)d_in[1];
    const float* mask = (const float*)d_in[2];
    float* out = (float*)d_out;

    void *p_a8 = nullptr, *p_b8 = nullptr;
    cudaGetSymbolAddress(&p_a8, g_a8);
    cudaGetSymbolAddress(&p_b8, g_b8);

    EncodeTiledFn enc = nullptr;
    {
        void* fn = nullptr;
        cudaDriverEntryPointQueryResult qr;
        cudaGetDriverEntryPoint("cuTensorMapEncodeTiled", &fn, cudaEnableDefault, &qr);
        enc = (EncodeTiledFn)fn;
    }
    CUtensorMap tma_a, tma_b;
    make_desc2d_u8(enc, &tma_a, p_a8, F_DIM, B_DIM, BK, BM);
    make_desc2d_u8(enc, &tma_b, p_b8, F_DIM, O_DIM, BK, BN);

    cudaFuncSetAttribute(sgxfl_gemm_kernel, cudaFuncAttributeMaxDynamicSharedMemorySize, GEMM_SMEM);
    cudaFuncSetAttribute(softmax_fix_kernel, cudaFuncAttributeMaxDynamicSharedMemorySize, SMX_SMEM);

    prep_a_kernel<<<(B_DIM * (size_t)F_DIM / 4) / 256, 256>>>(
        (const float4*)x, (const float4*)mask);
    prep_b_kernel<<<(O_DIM * (size_t)F_DIM / 4) / 256, 256>>>(
        (const float4*)w, (const float4*)mask);

    const int grid = (B_DIM / BM) * (O_DIM / BN);  // 32*125 = 4000
    sgxfl_gemm_kernel<<<grid, GEMM_THREADS, GEMM_SMEM>>>(tma_a, tma_b, out);

    softmax_fix_kernel<<<B_DIM, SMX_THREADS, SMX_SMEM>>>(out, x, mask);
}

// round 6
// speedup vs baseline: 2.9543x; 2.9543x over previous
#include <cuda_runtime.h>
#include <cuda.h>
#include <cuda_fp16.h>
#include <cstdint>
#include <cstddef>

// ---------------------------------------------------------------------------
// Problem constants
// ---------------------------------------------------------------------------
#define B_DIM 4096
#define F_DIM 4096
#define O_DIM 32000

// Scratch (device globals: allocation-free rule)
__device__ __half g_a16[(size_t)B_DIM * F_DIM];   // fp16 a = x - mask (2^-11 rel err)
__device__ __half g_b16[(size_t)O_DIM * F_DIM];   // fp16 b = quant(w) - mask (EXACT)

// ---------------------------------------------------------------------------
// PTX helpers (baseline-PTX only: toolchain targets compute_103, no tcgen05.
// R4/R5 established: fp8 + int8 mma.sync are EMULATED on this path; only
// fp16/bf16 HMMA is native. fp16 accum = double rate is the remaining lever.)
// ---------------------------------------------------------------------------
__device__ __forceinline__ uint32_t smem_u32(const void* p) {
    uint32_t a;
    asm("{ .reg .u64 t; cvta.to.shared.u64 t, %1; cvt.u32.u64 %0, t; }"
        : "=r"(a) : "l"(p));
    return a;
}

__device__ __forceinline__ uint32_t elect1() {
    uint32_t r;
    asm volatile(
        "{\n\t.reg .pred p;\n\telect.sync _|p, 0xFFFFFFFF;\n\tselp.b32 %0, 1, 0, p;\n\t}"
        : "=r"(r));
    return r;
}

#define MBARRIER_INIT(addr, cnt) \
    asm volatile("mbarrier.init.shared.b64 [%0], %1;" :: "r"((uint32_t)(addr)), "r"((uint32_t)(cnt)) : "memory")

#define MBARRIER_ARRIVE(addr) \
    asm volatile("mbarrier.arrive.shared.b64 _, [%0];" :: "r"((uint32_t)(addr)) : "memory")

#define MBARRIER_EXPECT_TX(addr, bytes) \
    asm volatile("mbarrier.arrive.expect_tx.shared.b64 _, [%0], %1;" :: "r"((uint32_t)(addr)), "r"((uint32_t)(bytes)) : "memory")

#define MBARRIER_WAIT_PARITY(mbar, par) do { \
    uint32_t _m = (uint32_t)(mbar); uint32_t _p = (uint32_t)(par); uint32_t _d; \
    asm volatile("{\n\t.reg .pred p;\n\t" \
        "mbarrier.try_wait.parity.acquire.cta.shared::cta.b64 p, [%1], %2;\n\t" \
        "selp.b32 %0, 1, 0, p;\n\t}" : "=r"(_d) : "r"(_m), "r"(_p) : "memory"); \
    if (!_d) { \
        asm volatile("{\n\t.reg .pred P1;\n\t" \
            "WL_%=:\n\t" \
            "mbarrier.try_wait.parity.acquire.cta.shared::cta.b64 P1, [%0], %1, 0x989680;\n\t" \
            "@P1 bra.uni WD_%=;\n\t" \
            "bra.uni WL_%=;\n\t" \
            "WD_%=:\n\t}" :: "r"(_m), "r"(_p) : "memory"); \
    } \
} while (0)

#define MBARRIER_WAIT_PARITY_RELAXED(mbar, par) do { \
    uint32_t _m = (uint32_t)(mbar); uint32_t _p = (uint32_t)(par); uint32_t _d; \
    asm volatile("{\n\t.reg .pred p;\n\t" \
        "mbarrier.try_wait.parity.relaxed.cta.shared::cta.b64 p, [%1], %2, 0x989680;\n\t" \
        "selp.b32 %0, 1, 0, p;\n\t}" : "=r"(_d) : "r"(_m), "r"(_p) : "memory"); \
    if (!_d) { \
        asm volatile("{\n\t.reg .pred P1;\n\t" \
            "WL_%=:\n\t" \
            "mbarrier.try_wait.parity.relaxed.cta.shared::cta.b64 P1, [%0], %1, 0x989680;\n\t" \
            "@P1 bra.uni WD_%=;\n\t" \
            "bra.uni WL_%=;\n\t" \
            "WD_%=:\n\t}" :: "r"(_m), "r"(_p) : "memory"); \
    } \
} while (0)

__device__ __forceinline__ void tma2d(uint32_t dst, const CUtensorMap* m, int cx, int cy, uint32_t bar) {
    asm volatile(
        "cp.async.bulk.tensor.2d.shared::cta.global.tile.mbarrier::complete_tx::bytes "
        "[%0], [%1, {%2, %3}], [%4];"
        :: "r"(dst), "l"(m), "r"(cx), "r"(cy), "r"(bar) : "memory");
}

#define LDMATRIX_X4(r0, r1, r2, r3, addr) \
    asm volatile("ldmatrix.sync.aligned.m8n8.x4.shared.b16 {%0,%1,%2,%3}, [%4];" \
                 : "=r"(r0), "=r"(r1), "=r"(r2), "=r"(r3) : "r"(addr))

// fp16 MMA with fp16 accumulation (2x rate vs f32 accum on legacy HMMA path)
#define MMAF16(c, a, b) \
    asm volatile("mma.sync.aligned.m16n8k16.row.col.f16.f16.f16.f16 " \
                 "{%0,%1}, {%2,%3,%4,%5}, {%6,%7}, {%0,%1};" \
                 : "+r"((c)[0]), "+r"((c)[1]) \
                 : "r"((a)[0]), "r"((a)[1]), "r"((a)[2]), "r"((a)[3]), \
                   "r"((b)[0]), "r"((b)[1]))

// ---------------------------------------------------------------------------
// Prep kernels
// ---------------------------------------------------------------------------
__global__ void prep_a_kernel(const float4* __restrict__ x, const float4* __restrict__ mask) {
    size_t i = (size_t)blockIdx.x * blockDim.x + threadIdx.x;  // < B*F/4
    float4 xv = x[i], mv = mask[i];
    __half2* o = reinterpret_cast<__half2*>(&g_a16[4 * i]);
    o[0] = __floats2half2_rn(xv.x - mv.x, xv.y - mv.y);
    o[1] = __floats2half2_rn(xv.z - mv.z, xv.w - mv.w);
}

__device__ __forceinline__ float quantw1(float w, float m) {
    float q = rintf(w * 128.0f) * 0.0078125f;     // round-half-even like jnp.round
    q = fminf(1.0f, fmaxf(-1.0f, q));
    return q - m;                                  // multiple of 1/128, EXACT in fp16
}

__global__ void prep_b_kernel(const float4* __restrict__ w, const float4* __restrict__ mask) {
    size_t i = (size_t)blockIdx.x * blockDim.x + threadIdx.x;  // < O*F/4
    float4 wv = w[i], mv = mask[i];
    __half2* o = reinterpret_cast<__half2*>(&g_b16[4 * i]);
    o[0] = __floats2half2_rn(quantw1(wv.x, mv.x), quantw1(wv.y, mv.y));
    o[1] = __floats2half2_rn(quantw1(wv.z, mv.z), quantw1(wv.w, mv.w));
}

// ---------------------------------------------------------------------------
// GEMM: logits[B, O] = a16 @ b16^T  (fp16 mma.sync, fp16 accum)
// Tiles: BM=128, BN=256, BK=64. 8 math warps (32x128 each) + 1 TMA warp.
// ---------------------------------------------------------------------------
static constexpr int BM = 128, BN = 256, BK = 64, STAGES = 4;
static constexpr int NCHUNK = F_DIM / BK;                          // 64
static constexpr uint32_t A_BYTES = BM * BK * 2;                   // 16384
static constexpr uint32_t B_BYTES = BN * BK * 2;                   // 32768
static constexpr uint32_t STAGE_BYTES = A_BYTES + B_BYTES;         // 49152
static constexpr uint32_t GEMM_SMEM = 1024 + STAGES * STAGE_BYTES; // 197632
static constexpr int GEMM_THREADS = 288;                           // 8 math + 1 producer warp

__global__ void __launch_bounds__(GEMM_THREADS, 1) sgxfl_gemm_kernel(
    const __grid_constant__ CUtensorMap tma_a,
    const __grid_constant__ CUtensorMap tma_b,
    float* __restrict__ out)
{
    extern __shared__ char smem[];
    const uint32_t sb = smem_u32(smem);
    const int tid = threadIdx.x;
    const int wid = tid >> 5, lid = tid & 31;

    // L2-friendly rasterization: GROUP_M=8 tiles of M per N sweep
    const int num_n = O_DIM / BN;   // 125
    const int GROUP = 8;
    const int cpg = GROUP * num_n;  // 1000
    const int g = blockIdx.x / cpg, r = blockIdx.x % cpg;
    const int m0 = (g * GROUP + (r % GROUP)) * BM;
    const int n0 = (r / GROUP) * BN;

    if (tid == 0) {
#pragma unroll
        for (int s = 0; s < STAGES; s++) {
            MBARRIER_INIT(sb + 16 * s, 1);       // full: tx-based
            MBARRIER_INIT(sb + 16 * s + 8, 8);   // empty: 8 math warps
        }
        asm volatile("fence.proxy.async.shared::cta;" ::: "memory");
    }
    __syncthreads();

    if (wid == 8) {
        // ---- TMA producer warp ----
        const uint32_t e1 = elect1();
        int st = 0, ph = 1;
        for (int i = 0; i < NCHUNK; i++) {
            MBARRIER_WAIT_PARITY_RELAXED(sb + 16 * st + 8, ph);
            if (e1) {
                MBARRIER_EXPECT_TX(sb + 16 * st, STAGE_BYTES);
                const uint32_t base = sb + 1024 + st * STAGE_BYTES;
                const int k0 = i * BK;
                tma2d(base,           &tma_a, k0, m0, sb + 16 * st);
                tma2d(base + A_BYTES, &tma_b, k0, n0, sb + 16 * st);
            }
            if (++st == STAGES) { st = 0; ph ^= 1; }
        }
        return;
    }

    // ---- Math warps (0..7): warp tile 32 (M) x 128 (N) ----
    const int wm = wid & 3;            // 0..3 -> M offset
    const int wn = wid >> 2;           // 0..1 -> N offset
    const int M0 = wm * 32;
    const int N0 = wn * 128;

    // ldmatrix per-lane offsets (SW128 swizzle: xor bits[4:6] by row&7)
    const uint32_t xrA  = (uint32_t)(lid & 7) << 4;
    const uint32_t khxA = (uint32_t)(lid >> 4) * 16;
    uint32_t rowA[2];
#pragma unroll
    for (int mi = 0; mi < 2; mi++)
        rowA[mi] = (uint32_t)(M0 + mi * 16 + (lid & 15)) * 128;
    const uint32_t xrB = (uint32_t)(lid & 7) << 4;
    const uint32_t khB = (uint32_t)((lid >> 3) & 1) * 16;
    uint32_t rowB[8];
#pragma unroll
    for (int p = 0; p < 8; p++)
        rowB[p] = (uint32_t)(N0 + p * 16 + (lid & 7) + (lid >> 4) * 8) * 128;

    // fp16 accumulators: 2 f16x2 regs per m16n8 tile
    uint32_t acc[2][16][2];
#pragma unroll
    for (int mi = 0; mi < 2; mi++)
#pragma unroll
        for (int nj = 0; nj < 16; nj++) {
            acc[mi][nj][0] = 0u;
            acc[mi][nj][1] = 0u;
        }

    int st = 0, ph = 0;
#pragma unroll 1
    for (int i = 0; i < NCHUNK; i++) {
        MBARRIER_WAIT_PARITY(sb + 16 * st, ph);
        const uint32_t base = sb + 1024 + st * STAGE_BYTES;
        const uint32_t sA = base, sB = base + A_BYTES;

#pragma unroll
        for (int k = 0; k < 4; k++) {
            const uint32_t colA = (uint32_t)(k * 32) + khxA;
            const uint32_t colB = (uint32_t)(k * 32) + khB;
            uint32_t af[2][4];
#pragma unroll
            for (int mi = 0; mi < 2; mi++) {
                LDMATRIX_X4(af[mi][0], af[mi][1], af[mi][2], af[mi][3],
                            sA + rowA[mi] + (colA ^ xrA));
            }
#pragma unroll
            for (int p = 0; p < 8; p++) {
                uint32_t b0[2], b1[2];
                LDMATRIX_X4(b0[0], b0[1], b1[0], b1[1],
                            sB + rowB[p] + (colB ^ xrB));
#pragma unroll
                for (int mi = 0; mi < 2; mi++) {
                    MMAF16(acc[mi][2 * p],     af[mi], b0);
                    MMAF16(acc[mi][2 * p + 1], af[mi], b1);
                }
            }
        }
        if (lid == 0) MBARRIER_ARRIVE(sb + 16 * st + 8);
        if (++st == STAGES) { st = 0; ph ^= 1; }
    }

    // ---- Epilogue: fp16 accum -> fp32 logits to gmem ----
    const int rg = lid >> 2;
    const int cg = (lid & 3) * 2;
#pragma unroll
    for (int mi = 0; mi < 2; mi++) {
        float* p0 = out + (size_t)(m0 + M0 + mi * 16 + rg) * O_DIM + (n0 + N0 + cg);
        float* p1 = p0 + (size_t)8 * O_DIM;
#pragma unroll
        for (int nj = 0; nj < 16; nj++) {
            float2 v0 = __half22float2(*reinterpret_cast<__half2*>(&acc[mi][nj][0]));
            float2 v1 = __half22float2(*reinterpret_cast<__half2*>(&acc[mi][nj][1]));
            *reinterpret_cast<float2*>(p0 + nj * 8) = v0;
            *reinterpret_cast<float2*>(p1 + nj * 8) = v1;
        }
    }
}

// ---------------------------------------------------------------------------
// Fused selective-correction + softmax.
// fp16-accum logits have error std <~1. Recompute all entries within DELTA of
// the row max exactly: a (fp32, from x-mask) dot b (fp16 g_b16, EXACT values).
// ---------------------------------------------------------------------------
__device__ __forceinline__ float fexp(float x) {  // x <= 0
    x = fmaxf(x, -87.0f);
    float t = x * 1.4426950408889634f;
    float fi = floorf(t);
    float f = t - fi;
    float p = 1.5403530e-4f;
    p = fmaf(p, f, 1.3333558e-3f);
    p = fmaf(p, f, 9.6181291e-3f);
    p = fmaf(p, f, 5.5504109e-2f);
    p = fmaf(p, f, 2.4022651e-1f);
    p = fmaf(p, f, 6.9314718e-1f);
    p = fmaf(p, f, 1.0f);
    int ei = (int)fi;
    float sc = __int_as_float((ei + 127) << 23);
    return p * sc;
}

static constexpr int   SMX_THREADS = 1024;
static constexpr int   SMX_NV4 = O_DIM / 4;        // 8000
static constexpr int   FIX_CAP = 2048;
static constexpr float FIX_DELTA = 40.0f;
// smem floats: row[32000] | a_row[4096] | red[64] | list[2048 ints] | cnt
static constexpr uint32_t SMX_ROW   = 0;
static constexpr uint32_t SMX_AROW  = O_DIM;                  // 32000
static constexpr uint32_t SMX_RED   = SMX_AROW + F_DIM;       // 36096
static constexpr uint32_t SMX_LIST  = SMX_RED + 64;           // 36160
static constexpr uint32_t SMX_CNT   = SMX_LIST + FIX_CAP;     // 38208
static constexpr uint32_t SMX_SMEM  = (SMX_CNT + 8) * 4;      // ~149.3 KB

__global__ void __launch_bounds__(SMX_THREADS, 1) softmax_fix_kernel(
    float* __restrict__ out,
    const float* __restrict__ x,
    const float* __restrict__ mask)
{
    extern __shared__ float sm[];
    float* srow  = sm + SMX_ROW;
    float* arow  = sm + SMX_AROW;
    float* red   = sm + SMX_RED;
    int*   list  = reinterpret_cast<int*>(sm + SMX_LIST);
    int*   cnt   = reinterpret_cast<int*>(sm + SMX_CNT);

    const int tid = threadIdx.x;
    const int wid = tid >> 5, lid = tid & 31;
    const int row = blockIdx.x;
    float* p = out + (size_t)row * O_DIM;
    float4* p4 = reinterpret_cast<float4*>(p);
    float4* s4 = reinterpret_cast<float4*>(srow);

    if (tid == 0) *cnt = 0;

    // stage a_row = x[row] - mask[row] (fp32, exact)
    {
        const float4* xr = reinterpret_cast<const float4*>(x + (size_t)row * F_DIM);
        const float4* mr = reinterpret_cast<const float4*>(mask + (size_t)row * F_DIM);
        for (int j = tid; j < F_DIM / 4; j += SMX_THREADS) {
            float4 xv = xr[j], mv = mr[j];
            reinterpret_cast<float4*>(arow)[j] =
                make_float4(xv.x - mv.x, xv.y - mv.y, xv.z - mv.z, xv.w - mv.w);
        }
    }

    // stage logits row, approximate max
    float m = -3.0e38f;
    for (int j = tid; j < SMX_NV4; j += SMX_THREADS) {
        float4 v = p4[j];
        s4[j] = v;
        m = fmaxf(m, fmaxf(fmaxf(v.x, v.y), fmaxf(v.z, v.w)));
    }
#pragma unroll
    for (int o = 16; o > 0; o >>= 1) m = fmaxf(m, __shfl_xor_sync(~0u, m, o));
    if (lid == 0) red[wid] = m;
    __syncthreads();
    float M0 = red[0];
#pragma unroll
    for (int k = 1; k < SMX_THREADS / 32; k++) M0 = fmaxf(M0, red[k]);

    // select candidates within DELTA of approx max
    const float thr = M0 - FIX_DELTA;
    for (int j = tid; j < O_DIM; j += SMX_THREADS) {
        if (srow[j] > thr) {
            int pos = atomicAdd(cnt, 1);
            if (pos < FIX_CAP) list[pos] = j;
        }
    }
    __syncthreads();
    int nsel = *cnt;
    if (nsel > FIX_CAP) nsel = FIX_CAP;

    // exact recompute of selected logits: one warp per dot, b from g_b16 (EXACT)
    for (int s = wid; s < nsel; s += SMX_THREADS / 32) {
        const int col = list[s];
        const uint4* b4 = reinterpret_cast<const uint4*>(g_b16 + (size_t)col * F_DIM);
        float part = 0.0f;
#pragma unroll 4
        for (int it = 0; it < F_DIM / (8 * 32); it++) {   // 16 iters
            const int c = it * 32 + lid;                   // chunk of 8 fp16
            uint4 v = b4[c];
            const float* ar = arow + 8 * c;
            float2 f0 = __half22float2(*reinterpret_cast<__half2*>(&v.x));
            float2 f1 = __half22float2(*reinterpret_cast<__half2*>(&v.y));
            float2 f2 = __half22float2(*reinterpret_cast<__half2*>(&v.z));
            float2 f3 = __half22float2(*reinterpret_cast<__half2*>(&v.w));
            part = fmaf(ar[0], f0.x, part);
            part = fmaf(ar[1], f0.y, part);
            part = fmaf(ar[2], f1.x, part);
            part = fmaf(ar[3], f1.y, part);
            part = fmaf(ar[4], f2.x, part);
            part = fmaf(ar[5], f2.y, part);
            part = fmaf(ar[6], f3.x, part);
            part = fmaf(ar[7], f3.y, part);
        }
#pragma unroll
        for (int o = 16; o > 0; o >>= 1) part += __shfl_xor_sync(~0u, part, o);
        if (lid == 0) srow[col] = part;
    }
    __syncthreads();

    // exact max over corrected row
    m = -3.0e38f;
    for (int j = tid; j < SMX_NV4; j += SMX_THREADS) {
        float4 v = s4[j];
        m = fmaxf(m, fmaxf(fmaxf(v.x, v.y), fmaxf(v.z, v.w)));
    }
#pragma unroll
    for (int o = 16; o > 0; o >>= 1) m = fmaxf(m, __shfl_xor_sync(~0u, m, o));
    if (lid == 0) red[wid] = m;
    __syncthreads();
    float M = red[0];
#pragma unroll
    for (int k = 1; k < SMX_THREADS / 32; k++) M = fmaxf(M, red[k]);

    // exp + sum
    float ssum = 0.0f;
    for (int j = tid; j < SMX_NV4; j += SMX_THREADS) {
        float4 v = s4[j];
        v.x = fexp(v.x - M); v.y = fexp(v.y - M);
        v.z = fexp(v.z - M); v.w = fexp(v.w - M);
        s4[j] = v;
        ssum += (v.x + v.y) + (v.z + v.w);
    }
#pragma unroll
    for (int o = 16; o > 0; o >>= 1) ssum += __shfl_xor_sync(~0u, ssum, o);
    if (lid == 0) red[32 + wid] = ssum;
    __syncthreads();
    float tot = 0.0f;
#pragma unroll
    for (int k = 0; k < SMX_THREADS / 32; k++) tot += red[32 + k];
    const float inv = 1.0f / tot;

    // normalize + write
    for (int j = tid; j < SMX_NV4; j += SMX_THREADS) {
        float4 v = s4[j];
        v.x *= inv; v.y *= inv; v.z *= inv; v.w *= inv;
        p4[j] = v;
    }
}

// ---------------------------------------------------------------------------
// Host launch
// ---------------------------------------------------------------------------
typedef CUresult (*EncodeTiledFn)(
    CUtensorMap*, CUtensorMapDataType, cuuint32_t, void*,
    const cuuint64_t*, const cuuint64_t*, const cuuint32_t*, const cuuint32_t*,
    CUtensorMapInterleave, CUtensorMapSwizzle, CUtensorMapL2promotion, CUtensorMapFloatOOBfill);

static void make_desc2d_f16(EncodeTiledFn enc, CUtensorMap* tm, void* base,
                            uint64_t d0, uint64_t d1, uint32_t b0, uint32_t b1) {
    cuuint64_t dims[2] = {d0, d1};
    cuuint64_t strides[1] = {d0 * 2};  // fp16
    cuuint32_t box[2] = {b0, b1};
    cuuint32_t es[2] = {1, 1};
    enc(tm, CU_TENSOR_MAP_DATA_TYPE_FLOAT16, 2, base, dims, strides, box, es,
        CU_TENSOR_MAP_INTERLEAVE_NONE, CU_TENSOR_MAP_SWIZZLE_128B,
        CU_TENSOR_MAP_L2_PROMOTION_L2_128B, CU_TENSOR_MAP_FLOAT_OOB_FILL_NONE);
}

extern "C" void kernel_launch(void* const* d_in, const int* in_sizes, int n_in,
                              void* d_out, int out_size) {
    const float* x    = (const float*)d_in[0];
    const float* w    = (const float*)d_in[1];
    const float* mask = (const float*)d_in[2];
    float* out = (float*)d_out;

    void *p_a = nullptr, *p_b = nullptr;
    cudaGetSymbolAddress(&p_a, g_a16);
    cudaGetSymbolAddress(&p_b, g_b16);

    EncodeTiledFn enc = nullptr;
    {
        void* fn = nullptr;
        cudaDriverEntryPointQueryResult qr;
        cudaGetDriverEntryPoint("cuTensorMapEncodeTiled", &fn, cudaEnableDefault, &qr);
        enc = (EncodeTiledFn)fn;
    }
    CUtensorMap tma_a, tma_b;
    make_desc2d_f16(enc, &tma_a, p_a, F_DIM, B_DIM, BK, BM);
    make_desc2d_f16(enc, &tma_b, p_b, F_DIM, O_DIM, BK, BN);

    cudaFuncSetAttribute(sgxfl_gemm_kernel, cudaFuncAttributeMaxDynamicSharedMemorySize, GEMM_SMEM);
    cudaFuncSetAttribute(softmax_fix_kernel, cudaFuncAttributeMaxDynamicSharedMemorySize, SMX_SMEM);

    prep_a_kernel<<<(B_DIM * (size_t)F_DIM / 4) / 256, 256>>>(
        (const float4*)x, (const float4*)mask);
    prep_b_kernel<<<(O_DIM * (size_t)F_DIM / 4) / 256, 256>>>(
        (const float4*)w, (const float4*)mask);

    const int grid = (B_DIM / BM) * (O_DIM / BN);  // 32*125 = 4000
    sgxfl_gemm_kernel<<<grid, GEMM_THREADS, GEMM_SMEM>>>(tma_a, tma_b, out);

    softmax_fix_kernel<<<B_DIM, SMX_THREADS, SMX_SMEM>>>(out, x, mask);
}